// round 6
// baseline (speedup 1.0000x reference)
#include <cuda_runtime.h>
#include <cuda_bf16.h>

#define HH 1024
#define WW 1024

static constexpr int NBLOCKS  = 1184;
static constexpr int NTHREADS = 256;
static constexpr int RB       = 8;          // rows per work item
static constexpr int RBLK     = HH / RB;    // 128 row-blocks per plane

__device__ float        g_part[NBLOCKS];
__device__ unsigned int g_count = 0;

typedef unsigned long long ull;

__device__ __forceinline__ ull pk(float lo, float hi) {
    ull r; asm("mov.b64 %0, {%1, %2};" : "=l"(r) : "f"(lo), "f"(hi)); return r;
}
__device__ __forceinline__ ull sub2(ull a, ull b) {
    ull r; asm("sub.rn.f32x2 %0, %1, %2;" : "=l"(r) : "l"(a), "l"(b)); return r;
}
__device__ __forceinline__ ull fma2(ull a, ull b, ull c) {
    ull r; asm("fma.rn.f32x2 %0, %1, %2, %3;" : "=l"(r) : "l"(a), "l"(b), "l"(c)); return r;
}
__device__ __forceinline__ void unpk(ull v, float& lo, float& hi) {
    asm("mov.b64 {%0, %1}, %2;" : "=f"(lo), "=f"(hi) : "l"(v));
}

// Load one row's quad + both halo values (right r, left l) via shuffles,
// with edge-column value substitution (verified formula from R5, rel_err=0).
__device__ __forceinline__ void load_row(const float* __restrict__ p, int j0,
                                         bool eL, bool eR, int lane,
                                         float4& v, float& r, float& l) {
    v = *(const float4*)(p + j0);
    const float sxd = __shfl_down_sync(0xffffffffu, v.x, 1);
    const float swu = __shfl_up_sync  (0xffffffffu, v.w, 1);
    float h = 0.f;
    if ((lane == 31 && !eR) || (lane == 0 && !eL))
        h = p[j0 + (lane == 31 ? 4 : -1)];
    r = (lane == 31) ? (eR ? v.w : h) : sxd;
    l = (lane == 0)  ? (eL ? v.x : h) : swu;
}

// Same, right halo only (for a row used solely as "c").
__device__ __forceinline__ void load_row_r(const float* __restrict__ p, int j0,
                                           bool eR, int lane,
                                           float4& v, float& r) {
    v = *(const float4*)(p + j0);
    const float sxd = __shfl_down_sync(0xffffffffu, v.x, 1);
    float h = 0.f;
    if (lane == 31 && !eR) h = p[j0 + 4];
    r = (lane == 31) ? (eR ? v.w : h) : sxd;
}

// Directed sum for one quad: offsets (0,1),(1,-1),(1,0),(1,1).
__device__ __forceinline__ void quadd(const float4 c, float cr,
                                      const float4 b, float bl, float br,
                                      ull& acc2) {
    const ull vp01 = pk(c.x, c.y), vp23 = pk(c.z, c.w);
    ull d;
    d = sub2(vp01, pk(c.y, c.z)); acc2 = fma2(d, d, acc2);   // right
    d = sub2(vp23, pk(c.w, cr));  acc2 = fma2(d, d, acc2);
    d = sub2(vp01, pk(b.x, b.y)); acc2 = fma2(d, d, acc2);   // down
    d = sub2(vp23, pk(b.z, b.w)); acc2 = fma2(d, d, acc2);
    const ull m12 = pk(b.y, b.z);
    d = sub2(vp01, pk(bl, b.x));  acc2 = fma2(d, d, acc2);   // down-left
    d = sub2(vp23, m12);          acc2 = fma2(d, d, acc2);
    d = sub2(vp01, m12);          acc2 = fma2(d, d, acc2);   // down-right
    d = sub2(vp23, pk(b.w, br));  acc2 = fma2(d, d, acc2);
}

__global__ __launch_bounds__(NTHREADS)
void lap_kernel(const float* __restrict__ f, float* __restrict__ out, int total_items) {
    ull acc2 = 0;
    const int stride = gridDim.x * blockDim.x;
    const int lane = threadIdx.x & 31;

    // Work item: (plane, row-block of RB rows, column-quad). cq fastest -> warp
    // lanes are 32 adjacent quads = 128 contiguous pixels, never straddling rows.
    for (int t = blockIdx.x * blockDim.x + threadIdx.x; t < total_items; t += stride) {
        const int cq = t & 255;
        const int rb = (t >> 8) & (RBLK - 1);
        const int pl = t >> 15;
        const float* __restrict__ base =
            f + ((size_t)pl << 20) + ((size_t)(rb * RB) << 10);
        const int j0 = cq << 2;
        const bool eL = (cq == 0), eR = (cq == 255);

        float4 cv; float crr;
        load_row_r(base, j0, eR, lane, cv, crr);

        if (rb == 0) {   // row 0: horizontal pairs count double (add once more)
            ull d;
            d = sub2(pk(cv.x, cv.y), pk(cv.y, cv.z)); acc2 = fma2(d, d, acc2);
            d = sub2(pk(cv.z, cv.w), pk(cv.w, crr));  acc2 = fma2(d, d, acc2);
        }

        #pragma unroll
        for (int k = 0; k < RB; k++) {
            if (rb * RB + k < HH - 1) {
                float4 bv; float brr, bll;
                load_row(base + ((size_t)(k + 1) << 10), j0, eL, eR, lane, bv, brr, bll);
                quadd(cv, crr, bv, bll, brr, acc2);
                cv = bv; crr = brr;
            } else {
                // row H-1: horizontal pairs only, counted double
                ull d;
                d = sub2(pk(cv.x, cv.y), pk(cv.y, cv.z));
                acc2 = fma2(d, d, acc2); acc2 = fma2(d, d, acc2);
                d = sub2(pk(cv.z, cv.w), pk(cv.w, crr));
                acc2 = fma2(d, d, acc2); acc2 = fma2(d, d, acc2);
            }
        }
    }

    float lo, hi; unpk(acc2, lo, hi);
    float acc = lo + hi;

    // ---- deterministic block reduction ----
    __shared__ float swarp[NTHREADS / 32];
    #pragma unroll
    for (int o = 16; o > 0; o >>= 1)
        acc += __shfl_down_sync(0xffffffffu, acc, o);
    if ((threadIdx.x & 31) == 0) swarp[threadIdx.x >> 5] = acc;
    __syncthreads();
    if (threadIdx.x < NTHREADS / 32) {
        float v = swarp[threadIdx.x];
        #pragma unroll
        for (int o = NTHREADS / 64; o > 0; o >>= 1)
            v += __shfl_down_sync(0xffu, v, o);
        if (threadIdx.x == 0) g_part[blockIdx.x] = v;
    }

    // ---- last-block final reduction ----
    __shared__ bool isLast;
    if (threadIdx.x == 0) {
        __threadfence();
        isLast = (atomicAdd(&g_count, 1u) == (unsigned)gridDim.x - 1u);
    }
    __syncthreads();
    if (isLast) {
        volatile float* gp = g_part;
        double v = 0.0;
        for (int idx = threadIdx.x; idx < NBLOCKS; idx += NTHREADS) v += (double)gp[idx];
        __shared__ double sd[NTHREADS];
        sd[threadIdx.x] = v;
        __syncthreads();
        #pragma unroll
        for (int o = NTHREADS / 2; o > 0; o >>= 1) {
            if (threadIdx.x < o) sd[threadIdx.x] += sd[threadIdx.x + o];
            __syncthreads();
        }
        if (threadIdx.x == 0) {
            out[0] = (float)(2.0 * sd[0]);
            g_count = 0;
        }
    }
}

extern "C" void kernel_launch(void* const* d_in, const int* in_sizes, int n_in,
                              void* d_out, int out_size) {
    const float* f = (const float*)d_in[0];
    const int n = in_sizes[0];
    const int planes = n >> 20;                 // 48
    const int total_items = planes << 15;       // planes * RBLK * 256
    lap_kernel<<<NBLOCKS, NTHREADS>>>(f, (float*)d_out, total_items);
}